// round 9
// baseline (speedup 1.0000x reference)
#include <cuda_runtime.h>
#include <cuda_bf16.h>
#include <cstdint>

#define HWTOT 9216
#define NBAT  2
#define CIN   128
#define CE    64
#define BM    128
#define BN    64
#define NITER (HWTOT / BN)   // 144

// ---------------- bf16 split scratch (device globals) ----------------
__device__ __nv_bfloat16 g_Qh[NBAT * HWTOT * CE];   // [n][i][c]
__device__ __nv_bfloat16 g_Ql[NBAT * HWTOT * CE];
__device__ __nv_bfloat16 g_Kh[NBAT * HWTOT * CE];   // [n][j][c]
__device__ __nv_bfloat16 g_Kl[NBAT * HWTOT * CE];
__device__ __nv_bfloat16 g_Vh[NBAT * CIN * HWTOT];  // [n][c][j]
__device__ __nv_bfloat16 g_Vl[NBAT * CIN * HWTOT];

// ---------------- helpers (plain PTX ISA only — no 'a' features) ----------------
__device__ __forceinline__ uint32_t smem_u32(const void* p) {
    uint32_t a;
    asm("{ .reg .u64 t; cvta.to.shared.u64 t, %1; cvt.u32.u64 %0, t; }" : "=r"(a) : "l"(p));
    return a;
}
__device__ __forceinline__ uint32_t swz(uint32_t x) { return x ^ ((x >> 3) & 0x70); }

#define CVT_BF16X2(r, a, b) \
    asm("cvt.rn.satfinite.bf16x2.f32 %0, %1, %2;" : "=r"(r) : "f"(b), "f"(a))  // low=a, high=b

#define CP_ASYNC16(d, s)  asm volatile("cp.async.cg.shared.global [%0], [%1], 16;" :: "r"(d), "l"(s) : "memory")
#define CP_COMMIT()       asm volatile("cp.async.commit_group;" ::: "memory")
#define CP_WAIT0()        asm volatile("cp.async.wait_group 0;" ::: "memory")

#define LDSM4(r0, r1, r2, r3, a) \
    asm volatile("ldmatrix.sync.aligned.m8n8.x4.shared.b16 {%0,%1,%2,%3}, [%4];" \
        : "=r"(r0), "=r"(r1), "=r"(r2), "=r"(r3) : "r"(a) : "memory")

#define MMA_BF16(d, a, b0, b1) \
    asm volatile("mma.sync.aligned.m16n8k16.row.col.f32.bf16.bf16.f32 " \
        "{%0,%1,%2,%3}, {%4,%5,%6,%7}, {%8,%9}, {%0,%1,%2,%3};" \
        : "+f"((d)[0]), "+f"((d)[1]), "+f"((d)[2]), "+f"((d)[3]) \
        : "r"((a)[0]), "r"((a)[1]), "r"((a)[2]), "r"((a)[3]), "r"(b0), "r"(b1))

// ---------------------------------------------------------------------------
// Projection: e1->Qh/Ql [i][c], e2->Kh/Kl [j][c], xa->Vh/Vl [c][j]
// ---------------------------------------------------------------------------
#define PROJ_SMEM ((32 * 128 + 128 * 128) * 4)

__global__ void __launch_bounds__(256, 2) proj_kernel(
    const float* __restrict__ x,
    const float* __restrict__ w1, const float* __restrict__ b1, const float* __restrict__ a1,
    const float* __restrict__ w2, const float* __restrict__ b2, const float* __restrict__ a2,
    const float* __restrict__ wa, const float* __restrict__ ba, const float* __restrict__ aa)
{
    extern __shared__ float sm[];
    float* ws = sm;            // [32][128]
    float* xs = sm + 32 * 128; // compute: [128][128]; staging: [32][132]

    const int n   = blockIdx.z;
    const int rg  = blockIdx.y;
    const int hw0 = blockIdx.x * 128;
    const int tid = threadIdx.x;
    const int rbase = rg * 32;

    const float* W; const float* B; const float* A; int cls;
    if (rbase < 64)       { W = w1 + rbase * CIN;          B = b1 + rbase;          A = a1; cls = 0; }
    else if (rbase < 128) { W = w2 + (rbase - 64) * CIN;   B = b2 + (rbase - 64);   A = a2; cls = 1; }
    else                  { W = wa + (rbase - 128) * CIN;  B = ba + (rbase - 128);  A = aa; cls = 2; }

    for (int idx = tid * 4; idx < 32 * 128; idx += 1024)
        *(float4*)&ws[idx] = *(const float4*)&W[idx];
    for (int idx = tid * 4; idx < 128 * 128; idx += 1024) {
        int c = idx >> 7, h = idx & 127;
        *(float4*)&xs[idx] = *(const float4*)&x[(n * CIN + c) * HWTOT + hw0 + h];
    }
    __syncthreads();

    const int w    = tid >> 5;
    const int lane = tid & 31;

    float acc[4][4];
#pragma unroll
    for (int r = 0; r < 4; r++)
#pragma unroll
        for (int q = 0; q < 4; q++) acc[r][q] = 0.f;

#pragma unroll 4
    for (int c = 0; c < CIN; c++) {
        float4 xv = *(float4*)&xs[c * 128 + 4 * lane];
#pragma unroll
        for (int rr = 0; rr < 4; rr++) {
            float wv = ws[(4 * w + rr) * 128 + c];
            acc[rr][0] += wv * xv.x;
            acc[rr][1] += wv * xv.y;
            acc[rr][2] += wv * xv.z;
            acc[rr][3] += wv * xv.w;
        }
    }

    const float slope = A[0];
    float y[4][4];
#pragma unroll
    for (int rr = 0; rr < 4; rr++) {
        const float bias = B[4 * w + rr];
#pragma unroll
        for (int q = 0; q < 4; q++) {
            float v = acc[rr][q] + bias;
            y[rr][q] = (v >= 0.f) ? v : slope * v;
        }
    }

    if (cls == 2) {
#pragma unroll
        for (int rr = 0; rr < 4; rr++) {
            const int R  = rbase - 128 + 4 * w + rr;
            const int hw = hw0 + 4 * lane;
            uint32_t h01, h23, l01, l23;
            CVT_BF16X2(h01, y[rr][0], y[rr][1]);
            CVT_BF16X2(h23, y[rr][2], y[rr][3]);
            float hf0 = __uint_as_float(h01 << 16), hf1 = __uint_as_float(h01 & 0xffff0000u);
            float hf2 = __uint_as_float(h23 << 16), hf3 = __uint_as_float(h23 & 0xffff0000u);
            CVT_BF16X2(l01, y[rr][0] - hf0, y[rr][1] - hf1);
            CVT_BF16X2(l23, y[rr][2] - hf2, y[rr][3] - hf3);
            size_t off = (size_t)(n * CIN + R) * HWTOT + hw;
            *(uint2*)((char*)g_Vh + off * 2) = make_uint2(h01, h23);
            *(uint2*)((char*)g_Vl + off * 2) = make_uint2(l01, l23);
        }
    } else {
        __syncthreads();
#pragma unroll
        for (int rr = 0; rr < 4; rr++)
#pragma unroll
            for (int q = 0; q < 4; q++)
                xs[(4 * w + rr) * 132 + 4 * lane + q] = y[rr][q];
        __syncthreads();

        const int h    = tid >> 1;
        const int half = tid & 1;
        float f[16];
#pragma unroll
        for (int k = 0; k < 16; k++)
            f[k] = xs[(16 * half + k) * 132 + h];

        uint32_t hp[8], lp[8];
#pragma unroll
        for (int p = 0; p < 8; p++) {
            uint32_t hh;
            CVT_BF16X2(hh, f[2 * p], f[2 * p + 1]);
            float h0 = __uint_as_float(hh << 16);
            float h1 = __uint_as_float(hh & 0xffff0000u);
            uint32_t ll;
            CVT_BF16X2(ll, f[2 * p] - h0, f[2 * p + 1] - h1);
            hp[p] = hh; lp[p] = ll;
        }
        const int col = ((cls == 0) ? rbase : rbase - 64) + 16 * half;
        size_t off = (size_t)(n * HWTOT + hw0 + h) * CE + col;
        __nv_bfloat16* dh = (cls == 0 ? g_Qh : g_Kh) + off;
        __nv_bfloat16* dl = (cls == 0 ? g_Ql : g_Kl) + off;
        *(uint4*)dh       = make_uint4(hp[0], hp[1], hp[2], hp[3]);
        *(uint4*)(dh + 8) = make_uint4(hp[4], hp[5], hp[6], hp[7]);
        *(uint4*)dl       = make_uint4(lp[0], lp[1], lp[2], lp[3]);
        *(uint4*)(dl + 8) = make_uint4(lp[4], lp[5], lp[6], lp[7]);
    }
}

// ---------------------------------------------------------------------------
// mma.sync flash attention (max-free softmax). Grid (72,2), 256 threads.
// Warp w owns rows m0=16w..m0+15. Q frags persistent in registers.
// QK: 3 independent accumulator chains. PV: nt2 pairs, ks-outer, interleaved.
// ---------------------------------------------------------------------------
#define OFF_QH 0
#define OFF_QL 16384
#define OFF_KH 32768     // [2][8192]
#define OFF_KL 49152
#define OFF_VH 65536     // [2][16384]
#define OFF_VL 98304
#define ATTN_SMEM 131072

__global__ void __launch_bounds__(256, 1) attn_kernel(float* __restrict__ out)
{
    extern __shared__ char smem[];
    const uint32_t sb = smem_u32(smem);

    const int n    = blockIdx.y;
    const int i0   = blockIdx.x * BM;
    const int tid  = threadIdx.x;
    const int wid  = tid >> 5;
    const int lane = tid & 31;
    const int m0   = wid * 16;

    // ---- Prologue: Q (persistent) + KV tile 0 ----
    {
        const char* qh = (const char*)g_Qh + (size_t)(n * HWTOT + i0) * CE * 2;
        const char* ql = (const char*)g_Ql + (size_t)(n * HWTOT + i0) * CE * 2;
        for (int i = tid; i < 1024; i += 256) {
            CP_ASYNC16(sb + OFF_QH + swz(i * 16), qh + (size_t)i * 16);
            CP_ASYNC16(sb + OFF_QL + swz(i * 16), ql + (size_t)i * 16);
        }
        const char* kh = (const char*)g_Kh + (size_t)(n * HWTOT) * CE * 2;
        const char* kl = (const char*)g_Kl + (size_t)(n * HWTOT) * CE * 2;
        for (int i = tid; i < 512; i += 256) {
            CP_ASYNC16(sb + OFF_KH + swz(i * 16), kh + (size_t)i * 16);
            CP_ASYNC16(sb + OFF_KL + swz(i * 16), kl + (size_t)i * 16);
        }
        const char* vh = (const char*)g_Vh + (size_t)n * CIN * HWTOT * 2;
        const char* vl = (const char*)g_Vl + (size_t)n * CIN * HWTOT * 2;
        for (int i = tid; i < 1024; i += 256) {
            int c = i >> 3, cb = (i & 7) * 16;
            CP_ASYNC16(sb + OFF_VH + swz(i * 16), vh + (size_t)c * HWTOT * 2 + cb);
            CP_ASYNC16(sb + OFF_VL + swz(i * 16), vl + (size_t)c * HWTOT * 2 + cb);
        }
        CP_COMMIT();
    }
    CP_WAIT0();
    __syncthreads();

    // ---- Load Q fragments (A, m16k16 per kstep) ----
    uint32_t qh[4][4], ql[4][4];
    {
        const int mrow = (lane & 7) + ((lane >> 3) & 1) * 8;
        const int cb   = (lane >> 4) * 16;
#pragma unroll
        for (int s = 0; s < 4; s++) {
            uint32_t a = sb + OFF_QH + swz((uint32_t)(m0 + mrow) * 128 + s * 32 + cb);
            LDSM4(qh[s][0], qh[s][1], qh[s][2], qh[s][3], a);
            a = sb + OFF_QL + swz((uint32_t)(m0 + mrow) * 128 + s * 32 + cb);
            LDSM4(ql[s][0], ql[s][1], ql[s][2], ql[s][3], a);
        }
    }

    float o[16][4];
#pragma unroll
    for (int i = 0; i < 16; i++)
#pragma unroll
        for (int q = 0; q < 4; q++) o[i][q] = 0.f;
    float lacc0 = 0.f, lacc1 = 0.f;

    const int brow = lane & 7;
    const int bcb  = (lane >> 3) * 16;

    for (int t = 0; t < NITER; t++) {
        const int buf = t & 1;
        if (t) { CP_WAIT0(); }
        __syncthreads();

        // Prefetch KV(t+1)
        if (t + 1 < NITER) {
            const int nb = (t + 1) & 1;
            const int j1 = (t + 1) * BN;
            const char* kh = (const char*)g_Kh + (size_t)(n * HWTOT + j1) * CE * 2;
            const char* kl = (const char*)g_Kl + (size_t)(n * HWTOT + j1) * CE * 2;
            for (int i = tid; i < 512; i += 256) {
                CP_ASYNC16(sb + OFF_KH + nb * 8192 + swz(i * 16), kh + (size_t)i * 16);
                CP_ASYNC16(sb + OFF_KL + nb * 8192 + swz(i * 16), kl + (size_t)i * 16);
            }
            const char* vh = (const char*)g_Vh + ((size_t)n * CIN * HWTOT + j1) * 2;
            const char* vl = (const char*)g_Vl + ((size_t)n * CIN * HWTOT + j1) * 2;
            for (int i = tid; i < 1024; i += 256) {
                int c = i >> 3, cb2 = (i & 7) * 16;
                CP_ASYNC16(sb + OFF_VH + nb * 16384 + swz(i * 16), vh + (size_t)c * HWTOT * 2 + cb2);
                CP_ASYNC16(sb + OFF_VL + nb * 16384 + swz(i * 16), vl + (size_t)c * HWTOT * 2 + cb2);
            }
            CP_COMMIT();
        }

        // ---- QK + exp + pack: S strip m16 x 64 ----
        const uint32_t kbh = sb + OFF_KH + buf * 8192;
        const uint32_t kbl = sb + OFF_KL + buf * 8192;
        uint32_t ph[4][4], pl[4][4];

#pragma unroll
        for (int nt = 0; nt < 8; nt++) {
            uint32_t bh[8], bl[8];
            const uint32_t o0 = swz((uint32_t)(nt * 8 + brow) * 128 + bcb);
            const uint32_t o1 = swz((uint32_t)(nt * 8 + brow) * 128 + bcb + 64);
            LDSM4(bh[0], bh[1], bh[2], bh[3], kbh + o0);
            LDSM4(bh[4], bh[5], bh[6], bh[7], kbh + o1);
            LDSM4(bl[0], bl[1], bl[2], bl[3], kbl + o0);
            LDSM4(bl[4], bl[5], bl[6], bl[7], kbl + o1);

            // 3 independent accumulator chains (hh, hl, lh)
            float sa[4] = {0.f, 0.f, 0.f, 0.f};
            float sb2[4] = {0.f, 0.f, 0.f, 0.f};
            float sc2[4] = {0.f, 0.f, 0.f, 0.f};
#pragma unroll
            for (int ks = 0; ks < 4; ks++) {
                MMA_BF16(sa,  qh[ks], bh[2 * ks], bh[2 * ks + 1]);
                MMA_BF16(sb2, qh[ks], bl[2 * ks], bl[2 * ks + 1]);
                MMA_BF16(sc2, ql[ks], bh[2 * ks], bh[2 * ks + 1]);
            }
            float s0 = sa[0] + sb2[0] + sc2[0];
            float s1 = sa[1] + sb2[1] + sc2[1];
            float s2 = sa[2] + sb2[2] + sc2[2];
            float s3 = sa[3] + sb2[3] + sc2[3];

            float e0 = __expf(s0), e1 = __expf(s1);
            float e2 = __expf(s2), e3 = __expf(s3);
            lacc0 += e0 + e1;
            lacc1 += e2 + e3;
            uint32_t h01, h23;
            CVT_BF16X2(h01, e0, e1);
            CVT_BF16X2(h23, e2, e3);
            float r0 = e0 - __uint_as_float(h01 << 16);
            float r1 = e1 - __uint_as_float(h01 & 0xffff0000u);
            float r2 = e2 - __uint_as_float(h23 << 16);
            float r3 = e3 - __uint_as_float(h23 & 0xffff0000u);
            uint32_t l01, l23;
            CVT_BF16X2(l01, r0, r1);
            CVT_BF16X2(l23, r2, r3);
            const int ks2 = nt >> 1, sl = (nt & 1) * 2;
            ph[ks2][sl] = h01; ph[ks2][sl + 1] = h23;
            pl[ks2][sl] = l01; pl[ks2][sl + 1] = l23;
        }

        // ---- PV: O += P V  (nt2 pairs, ks-outer, interleaved chains) ----
        const uint32_t vbh = sb + OFF_VH + buf * 16384;
        const uint32_t vbl = sb + OFF_VL + buf * 16384;
#pragma unroll
        for (int cp = 0; cp < 8; cp++) {
            const int na = 2 * cp, nb2 = 2 * cp + 1;
            uint32_t vah[8], val[8], vbh2[8], vbl2[8];
            {
                const uint32_t a0 = swz((uint32_t)(na * 8 + brow) * 128 + bcb);
                const uint32_t a1 = swz((uint32_t)(na * 8 + brow) * 128 + bcb + 64);
                const uint32_t b0 = swz((uint32_t)(nb2 * 8 + brow) * 128 + bcb);
                const uint32_t b1 = swz((uint32_t)(nb2 * 8 + brow) * 128 + bcb + 64);
                LDSM4(vah[0], vah[1], vah[2], vah[3], vbh + a0);
                LDSM4(vah[4], vah[5], vah[6], vah[7], vbh + a1);
                LDSM4(vbh2[0], vbh2[1], vbh2[2], vbh2[3], vbh + b0);
                LDSM4(vbh2[4], vbh2[5], vbh2[6], vbh2[7], vbh + b1);
                LDSM4(val[0], val[1], val[2], val[3], vbl + a0);
                LDSM4(val[4], val[5], val[6], val[7], vbl + a1);
                LDSM4(vbl2[0], vbl2[1], vbl2[2], vbl2[3], vbl + b0);
                LDSM4(vbl2[4], vbl2[5], vbl2[6], vbl2[7], vbl + b1);
            }
#pragma unroll
            for (int ks = 0; ks < 4; ks++) {
                MMA_BF16(o[na],  ph[ks], vah[2 * ks],  vah[2 * ks + 1]);
                MMA_BF16(o[nb2], ph[ks], vbh2[2 * ks], vbh2[2 * ks + 1]);
                MMA_BF16(o[na],  ph[ks], val[2 * ks],  val[2 * ks + 1]);
                MMA_BF16(o[nb2], ph[ks], vbl2[2 * ks], vbl2[2 * ks + 1]);
                MMA_BF16(o[na],  pl[ks], vah[2 * ks],  vah[2 * ks + 1]);
                MMA_BF16(o[nb2], pl[ks], vbh2[2 * ks], vbh2[2 * ks + 1]);
            }
        }
    }

    // ---- Epilogue ----
    lacc0 += __shfl_xor_sync(0xffffffffu, lacc0, 1);
    lacc0 += __shfl_xor_sync(0xffffffffu, lacc0, 2);
    lacc1 += __shfl_xor_sync(0xffffffffu, lacc1, 1);
    lacc1 += __shfl_xor_sync(0xffffffffu, lacc1, 2);
    const float inv0 = 1.f / lacc0;
    const float inv1 = 1.f / lacc1;
    const int r0 = i0 + m0 + (lane >> 2);
#pragma unroll
    for (int nt2 = 0; nt2 < 16; nt2++) {
        const int c = nt2 * 8 + (lane & 3) * 2;
        out[(size_t)(n * CIN + c) * HWTOT + r0]         = o[nt2][0] * inv0;
        out[(size_t)(n * CIN + c + 1) * HWTOT + r0]     = o[nt2][1] * inv0;
        out[(size_t)(n * CIN + c) * HWTOT + r0 + 8]     = o[nt2][2] * inv1;
        out[(size_t)(n * CIN + c + 1) * HWTOT + r0 + 8] = o[nt2][3] * inv1;
    }
}

extern "C" void kernel_launch(void* const* d_in, const int* in_sizes, int n_in,
                              void* d_out, int out_size)
{
    const float* x  = (const float*)d_in[0];
    const float* w1 = (const float*)d_in[1];
    const float* b1 = (const float*)d_in[2];
    const float* a1 = (const float*)d_in[3];
    const float* w2 = (const float*)d_in[4];
    const float* b2 = (const float*)d_in[5];
    const float* a2 = (const float*)d_in[6];
    const float* wa = (const float*)d_in[7];
    const float* ba = (const float*)d_in[8];
    const float* aa = (const float*)d_in[9];
    float* out = (float*)d_out;

    cudaFuncSetAttribute(proj_kernel, cudaFuncAttributeMaxDynamicSharedMemorySize, PROJ_SMEM);
    cudaFuncSetAttribute(attn_kernel, cudaFuncAttributeMaxDynamicSharedMemorySize, ATTN_SMEM);

    proj_kernel<<<dim3(HWTOT / 128, 8, NBAT), 256, PROJ_SMEM>>>(
        x, w1, b1, a1, w2, b2, a2, wa, ba, aa);
    attn_kernel<<<dim3(HWTOT / BM, NBAT), 256, ATTN_SMEM>>>(out);
}